// round 8
// baseline (speedup 1.0000x reference)
#include <cuda_runtime.h>
#include <cuda_bf16.h>

#define START_ID 62
#define PAD_ID   63
#define BATCH    512
#define SEQ      512
#define LBL      64
#define OV       16

typedef unsigned long long ull;

__device__ __forceinline__ float ex2f_(float x) {
    float y; asm("ex2.approx.f32 %0, %1;" : "=f"(y) : "f"(x)); return y;
}
__device__ __forceinline__ float lg2f_(float x) {
    float y; asm("lg2.approx.f32 %0, %1;" : "=f"(y) : "f"(x)); return y;
}
__device__ __forceinline__ ull fma2_(ull a, ull b, ull c) {
    ull d; asm("fma.rn.f32x2 %0, %1, %2, %3;" : "=l"(d) : "l"(a), "l"(b), "l"(c)); return d;
}
__device__ __forceinline__ ull add2_(ull a, ull b) {
    ull d; asm("add.rn.f32x2 %0, %1, %2;" : "=l"(d) : "l"(a), "l"(b)); return d;
}
__device__ __forceinline__ ull pack2_(float lo, float hi) {
    ull d; asm("mov.b64 %0, {%1, %2};" : "=l"(d) : "f"(lo), "f"(hi)); return d;
}
__device__ __forceinline__ void unpack2_(ull v, float& lo, float& hi) {
    asm("mov.b64 {%0, %1}, %2;" : "=f"(lo), "=f"(hi) : "l"(v));
}

// Block = one batch; warp k = segment k of 4. Segment k runs the recurrence
// over [s0, e] with s0 = max(0, tau_k - OV): burn-in via Birkhoff contraction
// of exp(T) makes the restart a constant shift; telescoping V-terms cancel the
// shifts exactly. When s0 clamps to 0 the segment is exact anyway.
__global__ __launch_bounds__(128, 3) void crf_loss_kernel(
    const float* __restrict__ ts,          // [B, S, L]
    const float* __restrict__ Tm,          // [L, L]
    const void*  __restrict__ labels_raw,  // [B, S] int32 or int64
    const void*  __restrict__ lengths_raw, // [B]    int32 or int64
    float* __restrict__ out)
{
    const int k   = threadIdx.x >> 5;            // segment 0..3
    const int tid = threadIdx.x & 31;            // lane: labels 2*tid, 2*tid+1
    const int b   = blockIdx.x;
    const unsigned FULL = 0xffffffffu;

    __shared__ __align__(16) float sp[4][2][LBL];  // per-warp P, double-buffered

    const float INV_LN2 = 1.44269504088896340736f;
    const float LN2     = 0.69314718055994530942f;

    // dtype detect: lengths viewed as int32 — word[1]==0 iff data is int64
    const int* l32 = (const int*)lengths_raw;
    const bool is64 = (l32[1] == 0);
    int len;
    if (is64) len = (int)(((const long long*)lengths_raw)[b]);
    else      len = l32[b];

    // ---- E = exp(T) packed along i-pairs for this lane's two output labels ----
    ull EA[32], EB[32];
    {
        const float2* Tm2 = (const float2*)Tm;   // [64][32] of float2
        #pragma unroll
        for (int q = 0; q < 32; ++q) {
            float2 r0 = Tm2[(2*q)     * 32 + tid];
            float2 r1 = Tm2[(2*q + 1) * 32 + tid];
            EA[q] = pack2_(__expf(r0.x), __expf(r1.x));
            EB[q] = pack2_(__expf(r0.y), __expf(r1.y));
        }
    }

    const float* tsb = ts + (size_t)b * SEQ * LBL;
    const float2* ts2 = (const float2*)tsb;      // [S][32] of float2

    const int  tauB = (k * len) >> 2;            // record boundary (k>0)
    const int  tauE = ((k + 1) * len) >> 2;      // emit boundary (k<3)
    const bool last = (k == 3);
    int s0 = (k == 0) ? 0 : (tauB - OV);
    if (s0 < 0) s0 = 0;
    const int  e = last ? (len - 1) : tauE;
    const bool true_init = (s0 == 0);

    // ---- init A at s0 ----
    float2 a0v = ts2[(size_t)s0 * 32 + tid];
    float A0, A1;
    if (true_init) {
        float2 t0v = ((const float2*)(Tm + START_ID * LBL))[tid];
        A0 = (a0v.x + t0v.x) * INV_LN2;
        A1 = (a0v.y + t0v.y) * INV_LN2;
    } else {
        A0 = a0v.x * INV_LN2;
        A1 = a0v.y * INV_LN2;
    }
    float Mcur = __shfl_sync(FULL, A0, 0);
    float Px = ex2f_(A0 - Mcur);
    float Py = ex2f_(A1 - Mcur);
    ((float2*)sp[k][0])[tid] = make_float2(Px, Py);

    const int n    = e - s0;
    const int urec = (k > 0) ? (tauB - s0) : -1;  // record step (0..OV)
    float Msave = Mcur, Psave = Px;               // covers urec==0

    // ---- emission prefetch ring, 4 deep, raw values, clamped to e ----
    float2 er[4];
    #pragma unroll
    for (int kk = 0; kk < 4; ++kk) {
        int tt = s0 + 1 + kk; if (tt > e) tt = e;
        er[kk] = ts2[(size_t)tt * 32 + tid];
    }

    int buf = 0;

    #pragma unroll 4
    for (int u = 1; u <= n; ++u) {
        const int slot = (u - 1) & 3;
        float ex = er[slot].x;
        float ey = er[slot].y;
        {
            int tt = s0 + u + 4; if (tt > e) tt = e;
            er[slot] = ts2[(size_t)tt * 32 + tid];
        }

        // shift bookkeeping off the critical path
        float p0 = __shfl_sync(FULL, Px, 0);
        float Kp = lg2f_(p0);
        float c0 = ex2f_(fmaf(ex, INV_LN2, -Kp));
        float c1 = ex2f_(fmaf(ey, INV_LN2, -Kp));
        Mcur += Kp;

        __syncwarp();

        // matvec: s_j = sum_i P[i] * E[i][j], packed f32x2 over i-pairs
        const ulonglong2* p4 = (const ulonglong2*)sp[k][buf];
        ull a0 = 0, a1 = 0, b0 = 0, b1 = 0;
        #pragma unroll
        for (int q = 0; q < 16; ++q) {
            ulonglong2 v = p4[q];
            a0 = fma2_(v.x, EA[2*q],     a0);
            a1 = fma2_(v.y, EA[2*q + 1], a1);
            b0 = fma2_(v.x, EB[2*q],     b0);
            b1 = fma2_(v.y, EB[2*q + 1], b1);
        }
        ull as = add2_(a0, a1), bs = add2_(b0, b1);
        float ax, ay, bx, by;
        unpack2_(as, ax, ay); unpack2_(bs, bx, by);

        Px = (ax + ay) * c0;
        Py = (bx + by) * c1;
        ((float2*)sp[k][buf ^ 1])[tid] = make_float2(Px, Py);
        buf ^= 1;

        if (u == urec) { Msave = Mcur; Psave = Px; }
    }

    // ---- segment contribution (log2 units) ----
    float fwd;
    if (last) {
        float tp0 = Tm[(2*tid)     * LBL + PAD_ID] * INV_LN2;
        float tp1 = Tm[(2*tid + 1) * LBL + PAD_ID] * INV_LN2;
        float z0 = Mcur + lg2f_(Px) + tp0;
        float z1 = Mcur + lg2f_(Py) + tp1;
        float m = fmaxf(z0, z1);
        #pragma unroll
        for (int o = 16; o > 0; o >>= 1)
            m = fmaxf(m, __shfl_xor_sync(FULL, m, o));
        float sv = ex2f_(z0 - m) + ex2f_(z1 - m);
        #pragma unroll
        for (int o = 16; o > 0; o >>= 1)
            sv += __shfl_xor_sync(FULL, sv, o);
        fwd = m + lg2f_(sv);
    } else {
        float pe0 = __shfl_sync(FULL, Px, 0);
        fwd = Mcur + lg2f_(pe0);
    }
    if (k > 0) {
        float ps0 = __shfl_sync(FULL, Psave, 0);
        fwd -= (Msave + lg2f_(ps0));
    }

    // ---- gold path score over [tauB, hi) ----
    const int hi = last ? len : tauE;
    float gsum = 0.0f;
    int last_label = 0;
    if (is64) {
        const long long* lab = (const long long*)labels_raw + (size_t)b * SEQ;
        for (int t = tauB + tid; t < hi; t += 32) {
            int lt = (int)lab[t];
            int pt = (t == 0) ? START_ID : (int)lab[t - 1];
            gsum += Tm[pt * LBL + lt] + tsb[(size_t)t * LBL + lt];
        }
        if (last && tid == 0) last_label = (int)lab[len - 1];
    } else {
        const int* lab = (const int*)labels_raw + (size_t)b * SEQ;
        for (int t = tauB + tid; t < hi; t += 32) {
            int lt = lab[t];
            int pt = (t == 0) ? START_ID : lab[t - 1];
            gsum += Tm[pt * LBL + lt] + tsb[(size_t)t * LBL + lt];
        }
        if (last && tid == 0) last_label = lab[len - 1];
    }
    #pragma unroll
    for (int o = 16; o > 0; o >>= 1)
        gsum += __shfl_xor_sync(FULL, gsum, o);

    if (tid == 0) {
        float gold = gsum + (last ? Tm[last_label * LBL + PAD_ID] : 0.0f);
        atomicAdd(out, (fwd * LN2 - gold) * (1.0f / (float)BATCH));
    }
}

extern "C" void kernel_launch(void* const* d_in, const int* in_sizes, int n_in,
                              void* d_out, int out_size)
{
    const float* ts      = (const float*)d_in[0];
    const float* Tm      = (const float*)d_in[1];
    const void*  labels  = d_in[2];
    const void*  lengths = d_in[3];
    float* out = (float*)d_out;

    cudaMemsetAsync(out, 0, sizeof(float));
    crf_loss_kernel<<<BATCH, 128>>>(ts, Tm, labels, lengths, out);
}

// round 9
// speedup vs baseline: 1.3260x; 1.3260x over previous
#include <cuda_runtime.h>
#include <cuda_bf16.h>

#define START_ID 62
#define PAD_ID   63
#define BATCH    512
#define SEQ      512
#define LBL      64
#define OV       12
#define SEGS     8
#define SEGW     64   // SEQ / SEGS

typedef unsigned long long ull;

__device__ __forceinline__ float ex2f_(float x) {
    float y; asm("ex2.approx.f32 %0, %1;" : "=f"(y) : "f"(x)); return y;
}
__device__ __forceinline__ float lg2f_(float x) {
    float y; asm("lg2.approx.f32 %0, %1;" : "=f"(y) : "f"(x)); return y;
}
__device__ __forceinline__ ull fma2_(ull a, ull b, ull c) {
    ull d; asm("fma.rn.f32x2 %0, %1, %2, %3;" : "=l"(d) : "l"(a), "l"(b), "l"(c)); return d;
}
__device__ __forceinline__ ull add2_(ull a, ull b) {
    ull d; asm("add.rn.f32x2 %0, %1, %2;" : "=l"(d) : "l"(a), "l"(b)); return d;
}
__device__ __forceinline__ ull pack2_(float lo, float hi) {
    ull d; asm("mov.b64 %0, {%1, %2};" : "=l"(d) : "f"(lo), "f"(hi)); return d;
}
__device__ __forceinline__ void unpack2_(ull v, float& lo, float& hi) {
    asm("mov.b64 {%0, %1}, %2;" : "=f"(lo), "=f"(hi) : "l"(v));
}

// Fixed-time segmentation: segment k covers absolute times [64k, 64(k+1)).
// CTA c: seg = c>>7 (seg-major order — guaranteed-full segs first), warp w
// handles batch (c&127)*4 + w. Segment k>0 restarts at 64k-OV (Birkhoff
// burn-in); telescoping V-terms at the tau boundaries cancel the unknown
// restart shifts exactly. Warps whose segment is beyond len exit immediately.
__global__ __launch_bounds__(128, 2) void crf_loss_kernel(
    const float* __restrict__ ts,          // [B, S, L]
    const float* __restrict__ Tm,          // [L, L]
    const void*  __restrict__ labels_raw,  // [B, S] int32 or int64
    const void*  __restrict__ lengths_raw, // [B]    int32 or int64
    float* __restrict__ out)
{
    const int w   = threadIdx.x >> 5;            // warp in block
    const int tid = threadIdx.x & 31;            // lane: labels 2*tid, 2*tid+1
    const int seg = blockIdx.x >> 7;             // 0..7
    const int b   = ((blockIdx.x & 127) << 2) + w;
    const unsigned FULL = 0xffffffffu;

    __shared__ __align__(16) float sp[4][2][LBL];  // per-warp P, double-buffered

    const float INV_LN2 = 1.44269504088896340736f;
    const float LN2     = 0.69314718055994530942f;

    // dtype detect: lengths viewed as int32 — word[1]==0 iff data is int64
    const int* l32 = (const int*)lengths_raw;
    const bool is64 = (l32[1] == 0);
    int len;
    if (is64) len = (int)(((const long long*)lengths_raw)[b]);
    else      len = l32[b];

    const int  tauB   = seg * SEGW;
    const int  tauE   = tauB + SEGW;
    const bool active = (seg == 0) || (len > tauB);
    if (!active) return;                         // no block syncs anywhere
    const bool last = (len <= tauE);

    const float* tsb = ts + (size_t)b * SEQ * LBL;
    const float2* ts2 = (const float2*)tsb;      // [S][32] of float2

    // ---- E = exp(T) packed along i-pairs for this lane's two output labels ----
    ull EA[32], EB[32];
    {
        const float2* Tm2 = (const float2*)Tm;   // [64][32] of float2
        #pragma unroll
        for (int q = 0; q < 32; ++q) {
            float2 r0 = Tm2[(2*q)     * 32 + tid];
            float2 r1 = Tm2[(2*q + 1) * 32 + tid];
            EA[q] = pack2_(__expf(r0.x), __expf(r1.x));
            EB[q] = pack2_(__expf(r0.y), __expf(r1.y));
        }
    }

    const int s0 = (seg == 0) ? 0 : (tauB - OV);
    const int e  = last ? (len - 1) : tauE;
    const int n  = e - s0;
    const int urec = (seg > 0) ? OV : -1;        // record step for V(tauB)

    // ---- init A at s0 (seg0: true init; else arbitrary restart) ----
    float2 a0v = ts2[(size_t)s0 * 32 + tid];
    float A0, A1;
    if (seg == 0) {
        float2 t0v = ((const float2*)(Tm + START_ID * LBL))[tid];
        A0 = (a0v.x + t0v.x) * INV_LN2;
        A1 = (a0v.y + t0v.y) * INV_LN2;
    } else {
        A0 = a0v.x * INV_LN2;
        A1 = a0v.y * INV_LN2;
    }
    float Mcur = __shfl_sync(FULL, A0, 0);
    float Px = ex2f_(A0 - Mcur);
    float Py = ex2f_(A1 - Mcur);
    ((float2*)sp[w][0])[tid] = make_float2(Px, Py);

    float Msave = Mcur, Psave = Px;

    // ---- emission prefetch ring, 4 deep, raw values, clamped to e ----
    float2 er[4];
    #pragma unroll
    for (int kk = 0; kk < 4; ++kk) {
        int tt = s0 + 1 + kk; if (tt > e) tt = e;
        er[kk] = ts2[(size_t)tt * 32 + tid];
    }

    int buf = 0;

    // ---- recurrence: renormalize only every 8th step ((u&7)==1 is
    //      compile-time under unroll 8); between renorms the correction
    //      c = exp2(e/ln2) depends only on prefetched data — fully
    //      off the serial chain. alpha = M + lg2(P) stays exact. ----
    #pragma unroll 8
    for (int u = 1; u <= n; ++u) {
        const int slot = (u - 1) & 3;
        float ex_ = er[slot].x;
        float ey_ = er[slot].y;
        {
            int tt = s0 + u + 4; if (tt > e) tt = e;
            er[slot] = ts2[(size_t)tt * 32 + tid];
        }

        float c0, c1;
        if ((u & 7) == 1) {
            float p0 = __shfl_sync(FULL, Px, 0);
            float Kp = lg2f_(p0);
            c0 = ex2f_(fmaf(ex_, INV_LN2, -Kp));
            c1 = ex2f_(fmaf(ey_, INV_LN2, -Kp));
            Mcur += Kp;
        } else {
            c0 = ex2f_(ex_ * INV_LN2);
            c1 = ex2f_(ey_ * INV_LN2);
        }

        __syncwarp();

        // matvec: s_j = sum_i P[i] * E[i][j], packed f32x2 over i-pairs
        const ulonglong2* p4 = (const ulonglong2*)sp[w][buf];
        ull a0 = 0, a1 = 0, b0 = 0, b1 = 0;
        #pragma unroll
        for (int q = 0; q < 16; ++q) {
            ulonglong2 v = p4[q];
            a0 = fma2_(v.x, EA[2*q],     a0);
            a1 = fma2_(v.y, EA[2*q + 1], a1);
            b0 = fma2_(v.x, EB[2*q],     b0);
            b1 = fma2_(v.y, EB[2*q + 1], b1);
        }
        ull as = add2_(a0, a1), bs = add2_(b0, b1);
        float ax, ay, bx, by;
        unpack2_(as, ax, ay); unpack2_(bs, bx, by);

        Px = (ax + ay) * c0;
        Py = (bx + by) * c1;
        ((float2*)sp[w][buf ^ 1])[tid] = make_float2(Px, Py);
        buf ^= 1;

        if (u == urec) { Msave = Mcur; Psave = Px; }
    }

    // ---- segment contribution (log2 units) ----
    float fwd;
    if (last) {
        float tp0 = Tm[(2*tid)     * LBL + PAD_ID] * INV_LN2;
        float tp1 = Tm[(2*tid + 1) * LBL + PAD_ID] * INV_LN2;
        float z0 = Mcur + lg2f_(Px) + tp0;
        float z1 = Mcur + lg2f_(Py) + tp1;
        float m = fmaxf(z0, z1);
        #pragma unroll
        for (int o = 16; o > 0; o >>= 1)
            m = fmaxf(m, __shfl_xor_sync(FULL, m, o));
        float sv = ex2f_(z0 - m) + ex2f_(z1 - m);
        #pragma unroll
        for (int o = 16; o > 0; o >>= 1)
            sv += __shfl_xor_sync(FULL, sv, o);
        fwd = m + lg2f_(sv);
    } else {
        float pe0 = __shfl_sync(FULL, Px, 0);
        fwd = Mcur + lg2f_(pe0);                 // +V(tauE)
    }
    if (seg > 0) {
        float ps0 = __shfl_sync(FULL, Psave, 0);
        fwd -= (Msave + lg2f_(ps0));             // -V(tauB)
    }

    // ---- gold path score over [tauB, min(tauE, len)) ----
    const int hi = last ? len : tauE;
    float gsum = 0.0f;
    int last_label = 0;
    if (is64) {
        const long long* lab = (const long long*)labels_raw + (size_t)b * SEQ;
        for (int t = tauB + tid; t < hi; t += 32) {
            int lt = (int)lab[t];
            int pt = (t == 0) ? START_ID : (int)lab[t - 1];
            gsum += Tm[pt * LBL + lt] + tsb[(size_t)t * LBL + lt];
        }
        if (last && tid == 0) last_label = (int)lab[len - 1];
    } else {
        const int* lab = (const int*)labels_raw + (size_t)b * SEQ;
        for (int t = tauB + tid; t < hi; t += 32) {
            int lt = lab[t];
            int pt = (t == 0) ? START_ID : lab[t - 1];
            gsum += Tm[pt * LBL + lt] + tsb[(size_t)t * LBL + lt];
        }
        if (last && tid == 0) last_label = lab[len - 1];
    }
    #pragma unroll
    for (int o = 16; o > 0; o >>= 1)
        gsum += __shfl_xor_sync(FULL, gsum, o);

    if (tid == 0) {
        float gold = gsum + (last ? Tm[last_label * LBL + PAD_ID] : 0.0f);
        atomicAdd(out, (fwd * LN2 - gold) * (1.0f / (float)BATCH));
    }
}

extern "C" void kernel_launch(void* const* d_in, const int* in_sizes, int n_in,
                              void* d_out, int out_size)
{
    const float* ts      = (const float*)d_in[0];
    const float* Tm      = (const float*)d_in[1];
    const void*  labels  = d_in[2];
    const void*  lengths = d_in[3];
    float* out = (float*)d_out;

    cudaMemsetAsync(out, 0, sizeof(float));
    crf_loss_kernel<<<SEGS * (BATCH / 4), 128>>>(ts, Tm, labels, lengths, out);
}